// round 10
// baseline (speedup 1.0000x reference)
#include <cuda_runtime.h>
#include <cuda_fp16.h>
#include <math.h>
#include <stdint.h>

#define N_NODES 50000
#define N_PAD   53248            // padded for int4 scan reads
#define N_EDGES 800000
#define E_TOT   (N_EDGES + N_NODES)   // with self loops
#define HID     128
#define NEG_SLOPE 0.2f
#define EPS 1e-16f

#define M_TILE   128
#define M_BLOCKS ((N_NODES + M_TILE - 1) / M_TILE)   // 391
#define A_P2 68               // half2 pitch for full-K A rows (64 + 4 pad)
#define B_P2 132              // half2 pitch for full-K B pair-rows
// sAh2 + sAl2 (128 x A_P2 each) + sB2 (64 x B_P2), half2 units (4 B)
#define GEMM_DYN_SMEM ((2 * M_TILE * A_P2 + 64 * B_P2) * 4)   // 103424 B

// ---------------- scratch (device globals; no allocation allowed) -----------
__device__ __half  g_xh[(size_t)N_NODES * HID];  // x = h @ W, fp16 (gather source)
__device__ float   g_h [(size_t)N_NODES * HID];  // layer activations (fp32)
__device__ float   g_as[N_NODES];
__device__ float   g_ad[N_NODES];
__device__ int     g_deg[N_PAD];
__device__ int     g_off[N_NODES + 1];
__device__ int     g_cur[N_NODES];
__device__ int     g_csrc[E_TOT];

// ---------------- helpers -----------------------------------------------------
__device__ __forceinline__ void mma_f16(float* d, const uint32_t* a, const uint32_t* b) {
    asm volatile(
        "mma.sync.aligned.m16n8k16.row.col.f32.f16.f16.f32 "
        "{%0,%1,%2,%3}, {%4,%5,%6,%7}, {%8,%9}, {%0,%1,%2,%3};"
        : "+f"(d[0]), "+f"(d[1]), "+f"(d[2]), "+f"(d[3])
        : "r"(a[0]), "r"(a[1]), "r"(a[2]), "r"(a[3]), "r"(b[0]), "r"(b[1]));
}

// ---------------- CSR build (4 edges/thread) ----------------------------------
__global__ void count_kernel(const int* __restrict__ ei) {
    int t = blockIdx.x * blockDim.x + threadIdx.x;     // over N_EDGES/4
    if (t >= N_EDGES / 4) return;
    int4 d4 = ((const int4*)(ei + N_EDGES))[t];
    atomicAdd(&g_deg[d4.x], 1);
    atomicAdd(&g_deg[d4.y], 1);
    atomicAdd(&g_deg[d4.z], 1);
    atomicAdd(&g_deg[d4.w], 1);
}
// single-block exclusive scan, 4 elements/thread; +1/node folds in self-loops
__global__ void scan_kernel() {
    __shared__ int warp_sums[32];
    __shared__ int s_carry;
    int tid = threadIdx.x, lane = tid & 31, wid = tid >> 5;
    if (tid == 0) { g_off[0] = 0; s_carry = 0; }
    __syncthreads();
    for (int base = 0; base < N_NODES; base += 4096) {
        int i = base + tid * 4;
        int4 v = *(const int4*)(g_deg + i);            // padded zeros beyond N_NODES
        int sl = (i < N_NODES) ? 1 : 0;                // self-loop (N_NODES % 4 == 0)
        int t0 = v.x + sl, t1 = t0 + v.y + sl, t2 = t1 + v.z + sl, t3 = t2 + v.w + sl;
        int x = t3;
        #pragma unroll
        for (int d = 1; d < 32; d <<= 1) {
            int t = __shfl_up_sync(0xffffffffu, x, d);
            if (lane >= d) x += t;
        }
        if (lane == 31) warp_sums[wid] = x;
        __syncthreads();
        if (wid == 0) {
            int w = warp_sums[lane];
            #pragma unroll
            for (int d = 1; d < 32; d <<= 1) {
                int t = __shfl_up_sync(0xffffffffu, w, d);
                if (lane >= d) w += t;
            }
            warp_sums[lane] = w;
        }
        __syncthreads();
        int excl = x - t3 + ((wid > 0) ? warp_sums[wid - 1] : 0) + s_carry;
        if (i < N_NODES) {
            g_off[i + 1] = excl + t0; g_cur[i + 0] = excl;
            g_off[i + 2] = excl + t1; g_cur[i + 1] = excl + t0;
            g_off[i + 3] = excl + t2; g_cur[i + 2] = excl + t1;
            g_off[i + 4] = excl + t3; g_cur[i + 3] = excl + t2;
        }
        __syncthreads();
        if (tid == 1023) s_carry = excl + t3;
        __syncthreads();
    }
}
__global__ void fill_kernel(const int* __restrict__ ei) {
    int t = blockIdx.x * blockDim.x + threadIdx.x;
    if (t < N_EDGES / 4) {
        int4 s4 = ((const int4*)ei)[t];
        int4 d4 = ((const int4*)(ei + N_EDGES))[t];
        g_csrc[atomicAdd(&g_cur[d4.x], 1)] = s4.x;
        g_csrc[atomicAdd(&g_cur[d4.y], 1)] = s4.y;
        g_csrc[atomicAdd(&g_cur[d4.z], 1)] = s4.z;
        g_csrc[atomicAdd(&g_cur[d4.w], 1)] = s4.w;
    } else {
        int node = t - N_EDGES / 4;
        if (node < N_NODES)
            g_csrc[atomicAdd(&g_cur[node], 1)] = node;   // self loop
    }
}

// ---------------- GEMM: x = h @ W, fp16 m16n8k16 2-term, fully-resident smem -
// Entire A (hi/lo) + entire B staged once; ONE barrier; unrolled MMA chain.
__global__ void __launch_bounds__(256, 2)
gemm_mma_kernel(const float* __restrict__ in, const float* __restrict__ W,
                const float* __restrict__ a_s, const float* __restrict__ a_d)
{
    extern __shared__ __half2 dsm[];
    __half2* sAh2 = dsm;                       // [M_TILE][A_P2]
    __half2* sAl2 = sAh2 + M_TILE * A_P2;      // [M_TILE][A_P2]
    __half2* sB2  = sAl2 + M_TILE * A_P2;      // [64][B_P2] pair-packed W

    __shared__ float s_as[HID], s_ad[HID];
    __shared__ float s_ps[2][M_TILE], s_pd[2][M_TILE];

    int tid = threadIdx.x, lane = tid & 31, wid = tid >> 5;
    int wm = wid & 3;        // warp M tile: 32 rows
    int wn = wid >> 2;       // warp N tile: 64 cols
    int m0 = blockIdx.x * M_TILE;
    int q = lane & 3, g = lane >> 2;

    for (int i = tid; i < HID; i += 256) { s_as[i] = a_s[i]; s_ad[i] = a_d[i]; }

    // ---- stage A: full 128x128 fp32 -> hi/lo half2; 2 threads per row ----
    {
        int r  = tid >> 1;
        int hh = tid & 1;              // k half: 0..63 or 64..127
        int gr = m0 + r;
        const float* src = in + (size_t)gr * HID + hh * 64;
        #pragma unroll
        for (int j = 0; j < 16; j++) {
            float4 v = make_float4(0.f, 0.f, 0.f, 0.f);
            if (gr < N_NODES) v = *(const float4*)(src + 4 * j);
            __half2 h01 = __floats2half2_rn(v.x, v.y);
            __half2 h23 = __floats2half2_rn(v.z, v.w);
            float2 f01 = __half22float2(h01);
            float2 f23 = __half22float2(h23);
            __half2 l01 = __floats2half2_rn(v.x - f01.x, v.y - f01.y);
            __half2 l23 = __floats2half2_rn(v.z - f23.x, v.w - f23.y);
            int c = hh * 32 + 2 * j;
            uint2 H; H.x = *(uint32_t*)&h01; H.y = *(uint32_t*)&h23;
            uint2 L; L.x = *(uint32_t*)&l01; L.y = *(uint32_t*)&l23;
            *(uint2*)&sAh2[r * A_P2 + c] = H;
            *(uint2*)&sAl2[r * A_P2 + c] = L;
        }
    }
    // ---- stage B: W[128][128] fp32 -> pair-packed half2 [64][B_P2] ----
    {
        int p  = tid >> 2;             // k pair 0..63
        int ng = (tid & 3) * 32;       // n column group
        const float* w0 = W + (size_t)(2 * p)     * HID + ng;
        const float* w1 = W + (size_t)(2 * p + 1) * HID + ng;
        #pragma unroll
        for (int j = 0; j < 8; j++) {
            float4 a = *(const float4*)(w0 + 4 * j);
            float4 b = *(const float4*)(w1 + 4 * j);
            __half2 p0 = __floats2half2_rn(a.x, b.x);
            __half2 p1 = __floats2half2_rn(a.y, b.y);
            __half2 p2 = __floats2half2_rn(a.z, b.z);
            __half2 p3 = __floats2half2_rn(a.w, b.w);
            uint4 o;
            o.x = *(uint32_t*)&p0; o.y = *(uint32_t*)&p1;
            o.z = *(uint32_t*)&p2; o.w = *(uint32_t*)&p3;
            *(uint4*)&sB2[p * B_P2 + ng + 4 * j] = o;
        }
    }
    __syncthreads();   // the only barrier before the epilogue

    float acc[2][8][4];
    #pragma unroll
    for (int mi = 0; mi < 2; mi++)
        #pragma unroll
        for (int ni = 0; ni < 8; ni++)
            #pragma unroll
            for (int t = 0; t < 4; t++) acc[mi][ni][t] = 0.f;

    const uint32_t* sAhu = (const uint32_t*)sAh2;
    const uint32_t* sAlu = (const uint32_t*)sAl2;
    const uint32_t* sBu  = (const uint32_t*)sB2;

    #pragma unroll
    for (int ks = 0; ks < 8; ks++) {
        int kp = ks * 8;
        uint32_t ah[2][4], al[2][4];
        #pragma unroll
        for (int mi = 0; mi < 2; mi++) {
            int r = wm * 32 + g + mi * 16;
            const uint32_t* ph = sAhu + r * A_P2;
            const uint32_t* pl = sAlu + r * A_P2;
            ah[mi][0] = ph[kp + q];        ah[mi][1] = ph[8 * A_P2 + kp + q];
            ah[mi][2] = ph[kp + q + 4];    ah[mi][3] = ph[8 * A_P2 + kp + q + 4];
            al[mi][0] = pl[kp + q];        al[mi][1] = pl[8 * A_P2 + kp + q];
            al[mi][2] = pl[kp + q + 4];    al[mi][3] = pl[8 * A_P2 + kp + q + 4];
        }
        #pragma unroll
        for (int ni = 0; ni < 8; ni++) {
            int cc = wn * 64 + ni * 8 + g;
            const uint32_t* pb = sBu + (kp + q) * B_P2 + cc;
            uint32_t b[2] = { pb[0], pb[4 * B_P2] };
            #pragma unroll
            for (int mi = 0; mi < 2; mi++) {
                mma_f16(acc[mi][ni], ah[mi], b);
                mma_f16(acc[mi][ni], al[mi], b);
            }
        }
    }

    // epilogue: store g_xh (fp16) + fused alpha partial dots (fp32, exact)
    #pragma unroll
    for (int mi = 0; mi < 2; mi++) {
        int rA_ = wm * 32 + g + mi * 16;
        int rB_ = rA_ + 8;
        int gA = m0 + rA_, gB = m0 + rB_;
        float sA_ = 0.f, dA_ = 0.f, sB_ = 0.f, dB_ = 0.f;
        #pragma unroll
        for (int ni = 0; ni < 8; ni++) {
            int cc = wn * 64 + ni * 8 + q * 2;
            float v0 = acc[mi][ni][0], v1 = acc[mi][ni][1];
            float v2 = acc[mi][ni][2], v3 = acc[mi][ni][3];
            sA_ += v0 * s_as[cc] + v1 * s_as[cc + 1];
            dA_ += v0 * s_ad[cc] + v1 * s_ad[cc + 1];
            sB_ += v2 * s_as[cc] + v3 * s_as[cc + 1];
            dB_ += v2 * s_ad[cc] + v3 * s_ad[cc + 1];
            if (gA < N_NODES)
                *(__half2*)(g_xh + (size_t)gA * HID + cc) = __floats2half2_rn(v0, v1);
            if (gB < N_NODES)
                *(__half2*)(g_xh + (size_t)gB * HID + cc) = __floats2half2_rn(v2, v3);
        }
        sA_ += __shfl_xor_sync(0xffffffffu, sA_, 1); sA_ += __shfl_xor_sync(0xffffffffu, sA_, 2);
        dA_ += __shfl_xor_sync(0xffffffffu, dA_, 1); dA_ += __shfl_xor_sync(0xffffffffu, dA_, 2);
        sB_ += __shfl_xor_sync(0xffffffffu, sB_, 1); sB_ += __shfl_xor_sync(0xffffffffu, sB_, 2);
        dB_ += __shfl_xor_sync(0xffffffffu, dB_, 1); dB_ += __shfl_xor_sync(0xffffffffu, dB_, 2);
        if (q == 0) {
            s_ps[wn][rA_] = sA_; s_pd[wn][rA_] = dA_;
            s_ps[wn][rB_] = sB_; s_pd[wn][rB_] = dB_;
        }
    }
    __syncthreads();
    if (tid < M_TILE) {
        int gm = m0 + tid;
        if (gm < N_NODES) {
            g_as[gm] = s_ps[0][tid] + s_ps[1][tid];
            g_ad[gm] = s_pd[0][tid] + s_pd[1][tid];
        }
    }
}

// ---------------- aggregation: warp/node, online softmax, smem pair bcast ----
__device__ __forceinline__ float leaky(float t) {
    return t > 0.f ? t : NEG_SLOPE * t;
}

__global__ __launch_bounds__(256) void agg_kernel(
    const float* __restrict__ bias, float* __restrict__ dout, int last)
{
    __shared__ uint2 s_ew[8][32];    // per-warp (w, src) pair table
    int node = (blockIdx.x * blockDim.x + threadIdx.x) >> 5;
    int lane = threadIdx.x & 31;
    int wid  = (threadIdx.x >> 5) & 7;
    if (node >= N_NODES) return;
    int start = g_off[node];
    int end   = g_off[node + 1];
    float adv = g_ad[node];

    float m = -INFINITY;
    float den = 0.f;
    float4 acc = make_float4(0.f, 0.f, 0.f, 0.f);

    for (int i0 = start; i0 < end; i0 += 32) {
        int n = end - i0; if (n > 32) n = 32;
        int   s_l = 0; float e_l = -INFINITY;
        if (lane < n) {
            s_l = g_csrc[i0 + lane];
            e_l = leaky(g_as[s_l] + adv);
        }
        float bm = e_l;
        #pragma unroll
        for (int o = 16; o; o >>= 1) bm = fmaxf(bm, __shfl_xor_sync(0xffffffffu, bm, o));
        if (bm > m) {
            float f = __expf(m - bm);
            acc.x *= f; acc.y *= f; acc.z *= f; acc.w *= f;
            den *= f;
            m = bm;
        }
        float w_l = (lane < n) ? __expf(e_l - m) : 0.f;
        den += w_l;
        s_ew[wid][lane] = make_uint2(__float_as_uint(w_l), (uint32_t)s_l);
        __syncwarp();
        for (int j = 0; j < n; j++) {
            uint2 ew = s_ew[wid][j];               // LDS.64 broadcast
            float w = __uint_as_float(ew.x);
            int   s = (int)ew.y;
            uint2 raw = *((const uint2*)(g_xh + (size_t)s * HID) + lane);
            float2 f0 = __half22float2(*(const __half2*)&raw.x);
            float2 f1 = __half22float2(*(const __half2*)&raw.y);
            acc.x += w * f0.x; acc.y += w * f0.y;
            acc.z += w * f1.x; acc.w += w * f1.y;
        }
        __syncwarp();
    }
    #pragma unroll
    for (int o = 16; o; o >>= 1) den += __shfl_xor_sync(0xffffffffu, den, o);
    float inv = 1.0f / (den + EPS);

    float4 b4 = *(const float4*)(bias + lane * 4);
    acc.x = acc.x * inv + b4.x; acc.y = acc.y * inv + b4.y;
    acc.z = acc.z * inv + b4.z; acc.w = acc.w * inv + b4.w;

    if (last) {
        *(float4*)(dout + (size_t)node * HID + lane * 4) = acc;
    } else {
        acc.x = fmaxf(acc.x, 0.f); acc.y = fmaxf(acc.y, 0.f);
        acc.z = fmaxf(acc.z, 0.f); acc.w = fmaxf(acc.w, 0.f);
        *(float4*)(g_h + (size_t)node * HID + lane * 4) = acc;
    }
}

// ---------------- launch -----------------------------------------------------
extern "C" void kernel_launch(void* const* d_in, const int* in_sizes, int n_in,
                              void* d_out, int out_size)
{
    const float* z     = (const float*)d_in[0];
    const int*   ei    = (const int*)  d_in[1];
    const float* Ws    = (const float*)d_in[2];
    const float* a_src = (const float*)d_in[3];
    const float* a_dst = (const float*)d_in[4];
    const float* bias  = (const float*)d_in[5];
    float* out = (float*)d_out;

    cudaFuncSetAttribute(gemm_mma_kernel, cudaFuncAttributeMaxDynamicSharedMemorySize,
                         GEMM_DYN_SMEM);

    float* d_gh;  cudaGetSymbolAddress((void**)&d_gh, g_h);
    int*   d_deg; cudaGetSymbolAddress((void**)&d_deg, g_deg);

    int warp_blocks = (N_NODES * 32 + 255) / 256;

    cudaMemsetAsync(d_deg, 0, N_PAD * sizeof(int));
    count_kernel<<<(N_EDGES / 4 + 255) / 256, 256>>>(ei);            // launch 1
    scan_kernel<<<1, 1024>>>();                                      // launch 2
    fill_kernel<<<(N_EDGES / 4 + N_NODES + 255) / 256, 256>>>(ei);   // launch 3

    for (int l = 0; l < 3; l++) {
        const float* in = (l == 0) ? z : d_gh;                       // launch 4 = gemm0
        gemm_mma_kernel<<<M_BLOCKS, 256, GEMM_DYN_SMEM>>>(
            in, Ws + (size_t)l * HID * HID, a_src + l * HID, a_dst + l * HID);
        agg_kernel<<<warp_blocks, 256>>>(bias + l * HID, out, l == 2);
    }
}

// round 11
// speedup vs baseline: 1.2171x; 1.2171x over previous
#include <cuda_runtime.h>
#include <cuda_fp16.h>
#include <math.h>
#include <stdint.h>

#define N_NODES 50000
#define N_PAD   53248            // padded for int4 scan reads
#define N_EDGES 800000
#define E_TOT   (N_EDGES + N_NODES)   // with self loops
#define HID     128
#define NEG_SLOPE 0.2f
#define EPS 1e-16f

#define M_TILE   128
#define M_BLOCKS ((N_NODES + M_TILE - 1) / M_TILE)   // 391
#define BK 32                 // k per chunk (16 half2 pairs)
#define A_P2 20               // half2 pitch for A tiles (conflict-free frag loads)
#define B_P2 132              // half2 pitch for B chunk
// sAh2 + sAl2 + sB2, in half2 (4 B) units
#define GEMM_DYN_SMEM ((2 * M_TILE * A_P2 + 16 * B_P2) * 4)   // 28928 B

// ---------------- scratch (device globals; no allocation allowed) -----------
__device__ __half  g_xh[(size_t)N_NODES * HID];  // x = h @ W, fp16 (gather source)
__device__ float   g_h [(size_t)N_NODES * HID];  // layer activations (fp32)
__device__ float   g_as[N_NODES];
__device__ float   g_ad[N_NODES];
__device__ __half2 g_wb[3 * 64 * HID];           // W pair-packed fp16: [l][k/2][n]
__device__ int     g_deg[N_PAD];
__device__ int     g_off[N_NODES + 1];
__device__ int     g_cur[N_NODES];
__device__ int     g_csrc[E_TOT];

// ---------------- helpers -----------------------------------------------------
__device__ __forceinline__ void mma_f16(float* d, const uint32_t* a, const uint32_t* b) {
    asm volatile(
        "mma.sync.aligned.m16n8k16.row.col.f32.f16.f16.f32 "
        "{%0,%1,%2,%3}, {%4,%5,%6,%7}, {%8,%9}, {%0,%1,%2,%3};"
        : "+f"(d[0]), "+f"(d[1]), "+f"(d[2]), "+f"(d[3])
        : "r"(a[0]), "r"(a[1]), "r"(a[2]), "r"(a[3]), "r"(b[0]), "r"(b[1]));
}

// ---------------- prep: W -> pair-packed fp16 image --------------------------
__global__ void prep_w_kernel(const float* __restrict__ Ws) {
    int idx = blockIdx.x * blockDim.x + threadIdx.x;   // over 3*64*128
    if (idx >= 3 * 64 * HID) return;
    int l   = idx / (64 * HID);
    int rem = idx - l * 64 * HID;
    int p = rem >> 7, n = rem & 127;
    const float* W = Ws + (size_t)l * HID * HID;
    g_wb[idx] = __floats2half2_rn(W[(2 * p) * HID + n], W[(2 * p + 1) * HID + n]);
}

// ---------------- CSR build (4 edges/thread) ----------------------------------
__global__ void count_kernel(const int* __restrict__ ei) {
    int t = blockIdx.x * blockDim.x + threadIdx.x;     // over N_EDGES/4
    if (t >= N_EDGES / 4) return;
    int4 d4 = ((const int4*)(ei + N_EDGES))[t];
    atomicAdd(&g_deg[d4.x], 1);
    atomicAdd(&g_deg[d4.y], 1);
    atomicAdd(&g_deg[d4.z], 1);
    atomicAdd(&g_deg[d4.w], 1);
}
// single-block exclusive scan, 4 elements/thread; +1/node folds in self-loops
__global__ void scan_kernel() {
    __shared__ int warp_sums[32];
    __shared__ int s_carry;
    int tid = threadIdx.x, lane = tid & 31, wid = tid >> 5;
    if (tid == 0) { g_off[0] = 0; s_carry = 0; }
    __syncthreads();
    for (int base = 0; base < N_NODES; base += 4096) {
        int i = base + tid * 4;
        int4 v = *(const int4*)(g_deg + i);            // padded zeros beyond N_NODES
        int sl = (i < N_NODES) ? 1 : 0;                // self-loop (N_NODES % 4 == 0)
        int t0 = v.x + sl, t1 = t0 + v.y + sl, t2 = t1 + v.z + sl, t3 = t2 + v.w + sl;
        int x = t3;
        #pragma unroll
        for (int d = 1; d < 32; d <<= 1) {
            int t = __shfl_up_sync(0xffffffffu, x, d);
            if (lane >= d) x += t;
        }
        if (lane == 31) warp_sums[wid] = x;
        __syncthreads();
        if (wid == 0) {
            int w = warp_sums[lane];
            #pragma unroll
            for (int d = 1; d < 32; d <<= 1) {
                int t = __shfl_up_sync(0xffffffffu, w, d);
                if (lane >= d) w += t;
            }
            warp_sums[lane] = w;
        }
        __syncthreads();
        int excl = x - t3 + ((wid > 0) ? warp_sums[wid - 1] : 0) + s_carry;
        if (i < N_NODES) {
            g_off[i + 1] = excl + t0; g_cur[i + 0] = excl;
            g_off[i + 2] = excl + t1; g_cur[i + 1] = excl + t0;
            g_off[i + 3] = excl + t2; g_cur[i + 2] = excl + t1;
            g_off[i + 4] = excl + t3; g_cur[i + 3] = excl + t2;
        }
        __syncthreads();
        if (tid == 1023) s_carry = excl + t3;
        __syncthreads();
    }
}
__global__ void fill_kernel(const int* __restrict__ ei) {
    int t = blockIdx.x * blockDim.x + threadIdx.x;
    if (t < N_EDGES / 4) {
        int4 s4 = ((const int4*)ei)[t];
        int4 d4 = ((const int4*)(ei + N_EDGES))[t];
        g_csrc[atomicAdd(&g_cur[d4.x], 1)] = s4.x;
        g_csrc[atomicAdd(&g_cur[d4.y], 1)] = s4.y;
        g_csrc[atomicAdd(&g_cur[d4.z], 1)] = s4.z;
        g_csrc[atomicAdd(&g_cur[d4.w], 1)] = s4.w;
    } else {
        int node = t - N_EDGES / 4;
        if (node < N_NODES)
            g_csrc[atomicAdd(&g_cur[node], 1)] = node;   // self loop
    }
}

// ---------------- GEMM: x = h @ W via mma.sync fp16 m16n8k16 (2-term) --------
// R9 version (measured 21.9us): chunked, register-prefetch pipelined.
__global__ void __launch_bounds__(256, 2)
gemm_mma_kernel(const float* __restrict__ in, const __half2* __restrict__ Wb,
                const float* __restrict__ a_s, const float* __restrict__ a_d)
{
    extern __shared__ __half2 dsm[];
    __half2* sAh2 = dsm;                       // [M_TILE][A_P2]
    __half2* sAl2 = sAh2 + M_TILE * A_P2;      // [M_TILE][A_P2]
    __half2* sB2  = sAl2 + M_TILE * A_P2;      // [16][B_P2]

    __shared__ float s_as[HID], s_ad[HID];
    __shared__ float s_ps[2][M_TILE], s_pd[2][M_TILE];

    int tid = threadIdx.x, lane = tid & 31, wid = tid >> 5;
    int wm = wid & 3;        // warp M tile: 32 rows
    int wn = wid >> 2;       // warp N tile: 64 cols
    int m0 = blockIdx.x * M_TILE;
    int q = lane & 3, g = lane >> 2;

    for (int i = tid; i < HID; i += 256) { s_as[i] = a_s[i]; s_ad[i] = a_d[i]; }

    int a_row = tid >> 3;          // + it*32
    int a_kq  = (tid & 7) * 4;     // k within chunk (floats)
    int a_p0  = (tid & 7) * 2;     // half2 pair col
    int b_row = tid >> 4;          // 0..15 (pair within chunk)
    int b_c16 = (tid & 15) * 8;    // half2 col base

    float acc[2][8][4];
    #pragma unroll
    for (int mi = 0; mi < 2; mi++)
        #pragma unroll
        for (int ni = 0; ni < 8; ni++)
            #pragma unroll
            for (int t = 0; t < 4; t++) acc[mi][ni][t] = 0.f;

    const uint4* wb4 = (const uint4*)Wb;       // [64][32] uint4

    float4 rA[4]; uint4 rB[2];
    #pragma unroll
    for (int it = 0; it < 4; it++) {
        int gr = m0 + it * 32 + a_row;
        rA[it] = make_float4(0.f, 0.f, 0.f, 0.f);
        if (gr < N_NODES) rA[it] = *(const float4*)(in + (size_t)gr * HID + a_kq);
    }
    rB[0] = wb4[b_row * 32 + (tid & 15) * 2];
    rB[1] = wb4[b_row * 32 + (tid & 15) * 2 + 1];

    #pragma unroll
    for (int c = 0; c < 4; c++) {
        #pragma unroll
        for (int it = 0; it < 4; it++) {
            float4 v = rA[it];
            __half2 h01 = __floats2half2_rn(v.x, v.y);
            __half2 h23 = __floats2half2_rn(v.z, v.w);
            float2 f01 = __half22float2(h01);
            float2 f23 = __half22float2(h23);
            __half2 l01 = __floats2half2_rn(v.x - f01.x, v.y - f01.y);
            __half2 l23 = __floats2half2_rn(v.z - f23.x, v.w - f23.y);
            int row = it * 32 + a_row;
            *(uint2*)&sAh2[row * A_P2 + a_p0] = *(uint2*)&h01;
            ((uint32_t*)&sAh2[row * A_P2 + a_p0])[1] = *(uint32_t*)&h23;
            *(uint32_t*)&sAl2[row * A_P2 + a_p0]     = *(uint32_t*)&l01;
            *(uint32_t*)&sAl2[row * A_P2 + a_p0 + 1] = *(uint32_t*)&l23;
        }
        *(uint4*)&sB2[b_row * B_P2 + b_c16]     = rB[0];
        *(uint4*)&sB2[b_row * B_P2 + b_c16 + 4] = rB[1];
        __syncthreads();

        if (c < 3) {
            #pragma unroll
            for (int it = 0; it < 4; it++) {
                int gr = m0 + it * 32 + a_row;
                rA[it] = make_float4(0.f, 0.f, 0.f, 0.f);
                if (gr < N_NODES)
                    rA[it] = *(const float4*)(in + (size_t)gr * HID + (c + 1) * BK + a_kq);
            }
            int pr = 16 * (c + 1) + b_row;
            rB[0] = wb4[pr * 32 + (tid & 15) * 2];
            rB[1] = wb4[pr * 32 + (tid & 15) * 2 + 1];
        }

        const uint32_t* sAhu = (const uint32_t*)sAh2;
        const uint32_t* sAlu = (const uint32_t*)sAl2;
        const uint32_t* sBu  = (const uint32_t*)sB2;
        #pragma unroll
        for (int ks = 0; ks < 2; ks++) {
            int kp = ks * 8;
            uint32_t ah[2][4], al[2][4];
            #pragma unroll
            for (int mi = 0; mi < 2; mi++) {
                int r = wm * 32 + g + mi * 16;
                const uint32_t* ph = sAhu + r * A_P2;
                const uint32_t* pl = sAlu + r * A_P2;
                ah[mi][0] = ph[kp + q];               ah[mi][1] = ph[8 * A_P2 + kp + q];
                ah[mi][2] = ph[kp + q + 4];           ah[mi][3] = ph[8 * A_P2 + kp + q + 4];
                al[mi][0] = pl[kp + q];               al[mi][1] = pl[8 * A_P2 + kp + q];
                al[mi][2] = pl[kp + q + 4];           al[mi][3] = pl[8 * A_P2 + kp + q + 4];
            }
            #pragma unroll
            for (int ni = 0; ni < 8; ni++) {
                int cc = wn * 64 + ni * 8 + g;
                const uint32_t* pb = sBu + (kp + q) * B_P2 + cc;
                uint32_t b[2] = { pb[0], pb[4 * B_P2] };
                #pragma unroll
                for (int mi = 0; mi < 2; mi++) {
                    mma_f16(acc[mi][ni], ah[mi], b);
                    mma_f16(acc[mi][ni], al[mi], b);
                }
            }
        }
        __syncthreads();
    }

    // epilogue: store g_xh (fp16) + fused alpha partial dots (fp32, exact)
    #pragma unroll
    for (int mi = 0; mi < 2; mi++) {
        int rA_ = wm * 32 + g + mi * 16;
        int rB_ = rA_ + 8;
        int gA = m0 + rA_, gB = m0 + rB_;
        float sA_ = 0.f, dA_ = 0.f, sB_ = 0.f, dB_ = 0.f;
        #pragma unroll
        for (int ni = 0; ni < 8; ni++) {
            int cc = wn * 64 + ni * 8 + q * 2;
            float v0 = acc[mi][ni][0], v1 = acc[mi][ni][1];
            float v2 = acc[mi][ni][2], v3 = acc[mi][ni][3];
            sA_ += v0 * s_as[cc] + v1 * s_as[cc + 1];
            dA_ += v0 * s_ad[cc] + v1 * s_ad[cc + 1];
            sB_ += v2 * s_as[cc] + v3 * s_as[cc + 1];
            dB_ += v2 * s_ad[cc] + v3 * s_ad[cc + 1];
            if (gA < N_NODES)
                *(__half2*)(g_xh + (size_t)gA * HID + cc) = __floats2half2_rn(v0, v1);
            if (gB < N_NODES)
                *(__half2*)(g_xh + (size_t)gB * HID + cc) = __floats2half2_rn(v2, v3);
        }
        sA_ += __shfl_xor_sync(0xffffffffu, sA_, 1); sA_ += __shfl_xor_sync(0xffffffffu, sA_, 2);
        dA_ += __shfl_xor_sync(0xffffffffu, dA_, 1); dA_ += __shfl_xor_sync(0xffffffffu, dA_, 2);
        sB_ += __shfl_xor_sync(0xffffffffu, sB_, 1); sB_ += __shfl_xor_sync(0xffffffffu, sB_, 2);
        dB_ += __shfl_xor_sync(0xffffffffu, dB_, 1); dB_ += __shfl_xor_sync(0xffffffffu, dB_, 2);
        if (q == 0) {
            s_ps[wn][rA_] = sA_; s_pd[wn][rA_] = dA_;
            s_ps[wn][rB_] = sB_; s_pd[wn][rB_] = dB_;
        }
    }
    __syncthreads();
    if (tid < M_TILE) {
        int gm = m0 + tid;
        if (gm < N_NODES) {
            g_as[gm] = s_ps[0][tid] + s_ps[1][tid];
            g_ad[gm] = s_pd[0][tid] + s_pd[1][tid];
        }
    }
}

// ---------------- aggregation: warp/node, online softmax, smem pair bcast ----
// R10 version (measured ~5us/layer faster than shfl broadcast).
__device__ __forceinline__ float leaky(float t) {
    return t > 0.f ? t : NEG_SLOPE * t;
}

__global__ __launch_bounds__(256) void agg_kernel(
    const float* __restrict__ bias, float* __restrict__ dout, int last)
{
    __shared__ uint2 s_ew[8][32];    // per-warp (w, src) pair table
    int node = (blockIdx.x * blockDim.x + threadIdx.x) >> 5;
    int lane = threadIdx.x & 31;
    int wid  = (threadIdx.x >> 5) & 7;
    if (node >= N_NODES) return;
    int start = g_off[node];
    int end   = g_off[node + 1];
    float adv = g_ad[node];

    float m = -INFINITY;
    float den = 0.f;
    float4 acc = make_float4(0.f, 0.f, 0.f, 0.f);

    for (int i0 = start; i0 < end; i0 += 32) {
        int n = end - i0; if (n > 32) n = 32;
        int   s_l = 0; float e_l = -INFINITY;
        if (lane < n) {
            s_l = g_csrc[i0 + lane];
            e_l = leaky(g_as[s_l] + adv);
        }
        float bm = e_l;
        #pragma unroll
        for (int o = 16; o; o >>= 1) bm = fmaxf(bm, __shfl_xor_sync(0xffffffffu, bm, o));
        if (bm > m) {
            float f = __expf(m - bm);
            acc.x *= f; acc.y *= f; acc.z *= f; acc.w *= f;
            den *= f;
            m = bm;
        }
        float w_l = (lane < n) ? __expf(e_l - m) : 0.f;
        den += w_l;
        s_ew[wid][lane] = make_uint2(__float_as_uint(w_l), (uint32_t)s_l);
        __syncwarp();
        for (int j = 0; j < n; j++) {
            uint2 ew = s_ew[wid][j];               // LDS.64 broadcast
            float w = __uint_as_float(ew.x);
            int   s = (int)ew.y;
            uint2 raw = *((const uint2*)(g_xh + (size_t)s * HID) + lane);
            float2 f0 = __half22float2(*(const __half2*)&raw.x);
            float2 f1 = __half22float2(*(const __half2*)&raw.y);
            acc.x += w * f0.x; acc.y += w * f0.y;
            acc.z += w * f1.x; acc.w += w * f1.y;
        }
        __syncwarp();
    }
    #pragma unroll
    for (int o = 16; o; o >>= 1) den += __shfl_xor_sync(0xffffffffu, den, o);
    float inv = 1.0f / (den + EPS);

    float4 b4 = *(const float4*)(bias + lane * 4);
    acc.x = acc.x * inv + b4.x; acc.y = acc.y * inv + b4.y;
    acc.z = acc.z * inv + b4.z; acc.w = acc.w * inv + b4.w;

    if (last) {
        *(float4*)(dout + (size_t)node * HID + lane * 4) = acc;
    } else {
        acc.x = fmaxf(acc.x, 0.f); acc.y = fmaxf(acc.y, 0.f);
        acc.z = fmaxf(acc.z, 0.f); acc.w = fmaxf(acc.w, 0.f);
        *(float4*)(g_h + (size_t)node * HID + lane * 4) = acc;
    }
}

// ---------------- launch -----------------------------------------------------
extern "C" void kernel_launch(void* const* d_in, const int* in_sizes, int n_in,
                              void* d_out, int out_size)
{
    const float* z     = (const float*)d_in[0];
    const int*   ei    = (const int*)  d_in[1];
    const float* Ws    = (const float*)d_in[2];
    const float* a_src = (const float*)d_in[3];
    const float* a_dst = (const float*)d_in[4];
    const float* bias  = (const float*)d_in[5];
    float* out = (float*)d_out;

    float*   d_gh;  cudaGetSymbolAddress((void**)&d_gh, g_h);
    __half2* d_wb;  cudaGetSymbolAddress((void**)&d_wb, g_wb);
    int*     d_deg; cudaGetSymbolAddress((void**)&d_deg, g_deg);

    int warp_blocks = (N_NODES * 32 + 255) / 256;

    cudaMemsetAsync(d_deg, 0, N_PAD * sizeof(int));
    prep_w_kernel<<<(3 * 64 * HID + 255) / 256, 256>>>(Ws);          // launch 1
    count_kernel<<<(N_EDGES / 4 + 255) / 256, 256>>>(ei);            // launch 2
    scan_kernel<<<1, 1024>>>();                                      // launch 3
    // launch 4 = gemm0 (ncu capture slot)
    gemm_mma_kernel<<<M_BLOCKS, 256, GEMM_DYN_SMEM>>>(z, d_wb, a_src, a_dst);
    fill_kernel<<<(N_EDGES / 4 + N_NODES + 255) / 256, 256>>>(ei);   // launch 5
    agg_kernel<<<warp_blocks, 256>>>(bias, out, 0);

    for (int l = 1; l < 3; l++) {
        gemm_mma_kernel<<<M_BLOCKS, 256, GEMM_DYN_SMEM>>>(
            d_gh, d_wb + (size_t)l * 64 * HID, a_src + l * HID, a_dst + l * HID);
        agg_kernel<<<warp_blocks, 256>>>(bias + l * HID, out, l == 2);
    }
}